// round 13
// baseline (speedup 1.0000x reference)
#include <cuda_runtime.h>
#include <cstdint>

#define B_ 16
#define T_ 8
#define C_ 2048
#define H_ 16
#define D_ 128
#define MAXSEQ 4096
#define QKV_N (3*C_)   // 6144
#define M_ (B_*T_)     // 128
#define SPLITS 8

// Scratch (no allocations allowed) -------------------------------------------
__device__ float  g_qkv[M_ * QKV_N];               // [b*T+t][3C]  q|k|v
__device__ float  g_y[M_ * C_];                    // attention output
__device__ float  g_part[B_*H_*SPLITS * 8 * 128];  // unnormalized O per split
__device__ float2 g_ml[B_*H_*SPLITS * 8];          // (m,l) per split per t
__device__ float  g_gp[6 * M_ * QKV_N];            // GEMM split-K partials

// ---------------------------------------------------------------------------
__device__ __forceinline__ float tf32f(float x) {
    uint32_t r; asm("cvt.rna.tf32.f32 %0, %1;" : "=r"(r) : "f"(x));
    return __uint_as_float(r);
}
// pack two floats to bf16x2: vlo -> low half (element k), vhi -> high (k+1)
__device__ __forceinline__ uint32_t bf2(float vlo, float vhi) {
    uint32_t r; asm("cvt.rn.bf16x2.f32 %0, %1, %2;" : "=r"(r) : "f"(vhi), "f"(vlo));
    return r;
}
__device__ __forceinline__ void mma8(float* d, uint32_t a0, uint32_t a2,
                                     uint32_t b0, uint32_t b1) {
    const uint32_t z = 0;
    asm volatile(
        "mma.sync.aligned.m16n8k8.row.col.f32.tf32.tf32.f32 "
        "{%0,%1,%2,%3}, {%4,%5,%6,%7}, {%8,%9}, {%0,%1,%2,%3};"
        : "+f"(d[0]), "+f"(d[1]), "+f"(d[2]), "+f"(d[3])
        : "r"(a0), "r"(z), "r"(a2), "r"(z), "r"(b0), "r"(b1));
}
__device__ __forceinline__ void mma16(float* d, const uint32_t* a,
                                      uint32_t b0, uint32_t b1) {
    asm volatile(
        "mma.sync.aligned.m16n8k16.row.col.f32.bf16.bf16.f32 "
        "{%0,%1,%2,%3}, {%4,%5,%6,%7}, {%8,%9}, {%0,%1,%2,%3};"
        : "+f"(d[0]), "+f"(d[1]), "+f"(d[2]), "+f"(d[3])
        : "r"(a[0]), "r"(a[1]), "r"(a[2]), "r"(a[3]), "r"(b0), "r"(b1));
}
__device__ __forceinline__ void cpa16(uint32_t dst, const void* src, int srcsize) {
    asm volatile("cp.async.cg.shared.global [%0], [%1], 16, %2;"
                 :: "r"(dst), "l"(src), "r"(srcsize) : "memory");
}
__device__ __forceinline__ void cpa_commit() {
    asm volatile("cp.async.commit_group;" ::: "memory");
}
__device__ __forceinline__ void cpa_wait0() {
    asm volatile("cp.async.wait_group 0;" ::: "memory");
}
__device__ __forceinline__ void cpa_wait1() {
    asm volatile("cp.async.wait_group 1;" ::: "memory");
}

// dummy: shifts ncu's capture window onto the QKV GEMM
__global__ void dummy_k() {}

// ---------------------------------------------------------------------------
// 3xBF16 GEMM (hh + hl + lh, mma.m16n8k16), split-K partial output (no atomics).
// CTA tile 128x128, BK=16, 256 threads, 8 warps (4m x 2n) of m32n64.
// smem per stage: A [8 kpair][2*128+4], B [8 kpair][2*128+4] (hi,lo u32 pairs).
#define MSu 260
#define BSu 260
#define STGu (8*MSu + 8*BSu)         // 4160 u32 per stage
#define G3SMEMB (2*STGu*4)           // 33280 B

__global__ void __launch_bounds__(256)
bf16_gemm(const float* __restrict__ A, const float* __restrict__ W,
          float* __restrict__ P, int N, int K, int kLen) {
    extern __shared__ float sh[];
    uint32_t* shu = (uint32_t*)sh;

    int tid  = threadIdx.x;
    int lane = tid & 31, w = tid >> 5;
    int g = lane >> 2, c4 = lane & 3;
    int n0 = blockIdx.x * 128;
    int k0 = blockIdx.z * kLen;
    int rem = K - k0;
    int iters = ((kLen < rem) ? kLen : rem) >> 4;
    int wm = (w & 3) * 32;            // warp grid 4 (m) x 2 (n)
    int wn = (w >> 2) * 64;

    // A loader: row = tid>>1 (0..127), k-half = (tid&1)*8 -> 4 kpairs
    int arow = tid >> 1, ah = (tid & 1) * 8;
    // B loader: warp w owns kpair w (rows 2w, 2w+1); lane covers 4 n-cols
    int bn4 = lane * 4, bkp = w;

    float acc[2][8][4];
    #pragma unroll
    for (int mt = 0; mt < 2; mt++)
        #pragma unroll
        for (int nt = 0; nt < 8; nt++)
            #pragma unroll
            for (int j = 0; j < 4; j++) acc[mt][nt][j] = 0.f;

    float4 ra0, ra1, rb0, rb1;

    // ---- prefetch iter 0 ----
    {
        const float* pa = A + (size_t)arow * K + k0 + ah;
        ra0 = *(const float4*)pa; ra1 = *(const float4*)(pa + 4);
        rb0 = *(const float4*)(W + (size_t)(k0 + 2*bkp)     * N + n0 + bn4);
        rb1 = *(const float4*)(W + (size_t)(k0 + 2*bkp + 1) * N + n0 + bn4);
    }
    // ---- convert + store stage 0 ----
    {
        uint32_t* as = shu;
        uint32_t* bs = shu + 8*MSu;
        float v[8] = {ra0.x, ra0.y, ra0.z, ra0.w, ra1.x, ra1.y, ra1.z, ra1.w};
        #pragma unroll
        for (int j = 0; j < 4; j++) {
            uint32_t hi = bf2(v[2*j], v[2*j+1]);
            float h0 = __uint_as_float(hi << 16);
            float h1 = __uint_as_float(hi & 0xffff0000u);
            uint32_t lo = bf2(v[2*j] - h0, v[2*j+1] - h1);
            int kp = (ah >> 1) + j;
            *(uint2*)(as + kp*MSu + 2*arow) = make_uint2(hi, lo);
        }
        float v0[4] = {rb0.x, rb0.y, rb0.z, rb0.w};
        float v1[4] = {rb1.x, rb1.y, rb1.z, rb1.w};
        #pragma unroll
        for (int q = 0; q < 4; q++) {
            uint32_t hi = bf2(v0[q], v1[q]);
            float h0 = __uint_as_float(hi << 16);
            float h1 = __uint_as_float(hi & 0xffff0000u);
            uint32_t lo = bf2(v0[q] - h0, v1[q] - h1);
            *(uint2*)(bs + bkp*BSu + 2*(bn4 + q)) = make_uint2(hi, lo);
        }
    }
    __syncthreads();

    for (int it = 0; it < iters; it++) {
        if (it + 1 < iters) {
            int kb = k0 + (it+1)*16;
            const float* pa = A + (size_t)arow * K + kb + ah;
            ra0 = *(const float4*)pa; ra1 = *(const float4*)(pa + 4);
            rb0 = *(const float4*)(W + (size_t)(kb + 2*bkp)     * N + n0 + bn4);
            rb1 = *(const float4*)(W + (size_t)(kb + 2*bkp + 1) * N + n0 + bn4);
        }
        // ---- compute on stage it&1 ----
        {
            const uint32_t* as = shu + (it & 1) * STGu;
            const uint32_t* bs = as + 8*MSu;
            uint32_t ahi[2][4], alo[2][4];
            #pragma unroll
            for (int mt = 0; mt < 2; mt++) {
                int m0 = wm + 16*mt + g;
                uint2 t00 = *(const uint2*)(as + c4*MSu     + 2*m0);
                uint2 t10 = *(const uint2*)(as + c4*MSu     + 2*(m0+8));
                uint2 t01 = *(const uint2*)(as + (c4+4)*MSu + 2*m0);
                uint2 t11 = *(const uint2*)(as + (c4+4)*MSu + 2*(m0+8));
                ahi[mt][0] = t00.x; ahi[mt][1] = t10.x; ahi[mt][2] = t01.x; ahi[mt][3] = t11.x;
                alo[mt][0] = t00.y; alo[mt][1] = t10.y; alo[mt][2] = t01.y; alo[mt][3] = t11.y;
            }
            #pragma unroll
            for (int nt = 0; nt < 8; nt++) {
                int nc = wn + 8*nt + g;
                uint2 b0 = *(const uint2*)(bs + c4*BSu     + 2*nc);
                uint2 b1 = *(const uint2*)(bs + (c4+4)*BSu + 2*nc);
                #pragma unroll
                for (int mt = 0; mt < 2; mt++) {
                    mma16(acc[mt][nt], ahi[mt], b0.x, b1.x);   // hh
                    mma16(acc[mt][nt], ahi[mt], b0.y, b1.y);   // hl
                    mma16(acc[mt][nt], alo[mt], b0.x, b1.x);   // lh
                }
            }
        }
        if (it + 1 < iters) {
            uint32_t* as = shu + ((it+1) & 1) * STGu;
            uint32_t* bs = as + 8*MSu;
            float v[8] = {ra0.x, ra0.y, ra0.z, ra0.w, ra1.x, ra1.y, ra1.z, ra1.w};
            #pragma unroll
            for (int j = 0; j < 4; j++) {
                uint32_t hi = bf2(v[2*j], v[2*j+1]);
                float h0 = __uint_as_float(hi << 16);
                float h1 = __uint_as_float(hi & 0xffff0000u);
                uint32_t lo = bf2(v[2*j] - h0, v[2*j+1] - h1);
                int kp = (ah >> 1) + j;
                *(uint2*)(as + kp*MSu + 2*arow) = make_uint2(hi, lo);
            }
            float v0[4] = {rb0.x, rb0.y, rb0.z, rb0.w};
            float v1[4] = {rb1.x, rb1.y, rb1.z, rb1.w};
            #pragma unroll
            for (int q = 0; q < 4; q++) {
                uint32_t hi = bf2(v0[q], v1[q]);
                float h0 = __uint_as_float(hi << 16);
                float h1 = __uint_as_float(hi & 0xffff0000u);
                uint32_t lo = bf2(v0[q] - h0, v1[q] - h1);
                *(uint2*)(bs + bkp*BSu + 2*(bn4 + q)) = make_uint2(hi, lo);
            }
        }
        __syncthreads();
    }

    // ---- epilogue: plain stores to split-private partial buffer ----
    float* dst = P + (size_t)blockIdx.z * ((size_t)M_ * N);
    #pragma unroll
    for (int mt = 0; mt < 2; mt++)
        #pragma unroll
        for (int nt = 0; nt < 8; nt++) {
            int m   = wm + 16*mt + g;
            int col = n0 + wn + 8*nt + 2*c4;
            *(float2*)&dst[(size_t)m * N + col] =
                make_float2(acc[mt][nt][0], acc[mt][nt][1]);
            *(float2*)&dst[(size_t)(m+8) * N + col] =
                make_float2(acc[mt][nt][2], acc[mt][nt][3]);
        }
}

// ---------------------------------------------------------------------------
// dst[m][n] = bias[n] + sum_s P[s][m][n]   (float4-vectorized)
__global__ void reduce_add(float* __restrict__ dst, const float* __restrict__ P,
                           const float* __restrict__ bias,
                           int N, int total4, int nsplits) {
    int i = blockIdx.x * blockDim.x + threadIdx.x;
    if (i >= total4) return;
    int n = (i << 2) % N;
    float4 s = *(const float4*)(bias + n);
    for (int sp = 0; sp < nsplits; sp++) {
        float4 p = ((const float4*)P)[(size_t)sp * total4 + i];
        s.x += p.x; s.y += p.y; s.z += p.z; s.w += p.w;
    }
    ((float4*)dst)[i] = s;
}

// ---------------------------------------------------------------------------
// Flash attention, split-S(8), tf32 mma, TILE=64, cp.async double-buffered.
// (unchanged from best round)
#define TILE 64
#define TS 132
#define PS 68
#define ASM_FLOATS (8*TS + 2*TILE*TS + 8*PS + 24)   // 74080 B

__global__ void __launch_bounds__(256, 3)
attn_kernel(const float* __restrict__ k_cache,
            const float* __restrict__ v_cache,
            const int* __restrict__ sp_ptr,
            const int* __restrict__ causal_ptr) {
    extern __shared__ float sm[];
    float* q    = sm;                   // 8 x TS
    float* Kbuf = sm + 8*TS;            // TILE x TS
    float* Vbuf = Kbuf + TILE*TS;       // TILE x TS
    float* p    = Vbuf + TILE*TS;       // 8 x PS
    float* mbuf = p + 8*PS;
    float* lbuf = mbuf + 8;
    float* cbuf = lbuf + 8;

    uint32_t Ku = (uint32_t)__cvta_generic_to_shared(Kbuf);
    uint32_t Vu = (uint32_t)__cvta_generic_to_shared(Vbuf);

    int tid  = threadIdx.x;
    int lane = tid & 31;
    int w    = tid >> 5;
    int bh    = blockIdx.x >> 3;
    int split = blockIdx.x & 7;
    int b = bh >> 4, h = bh & 15;
    int sp = *sp_ptr;
    int causal = *causal_ptr;
    int S = sp + T_;
    int SLEN = (S + SPLITS - 1) / SPLITS;
    int sb = split * SLEN;
    int se = min(S, sb + SLEN);
    int ntiles = (se > sb) ? (se - sb + TILE - 1) / TILE : 0;
    int g = lane >> 2, c4 = lane & 3;

    const float* kc = k_cache + (size_t)bh * MAXSEQ * D_;
    const float* vc = v_cache + (size_t)bh * MAXSEQ * D_;
    const float* kf = g_qkv + (size_t)b * T_ * QKV_N + C_   + h*D_;
    const float* vf = g_qkv + (size_t)b * T_ * QKV_N + 2*C_ + h*D_;

    if (tid < 8) { mbuf[tid] = -1e30f; lbuf[tid] = 0.f; }
    {
        int t = tid >> 5;
        int d = lane * 4;
        float4 v4 = *(const float4*)(g_qkv + (size_t)(b*T_ + t)*QKV_N + h*D_ + d);
        const float sc = 0.08838834764831845f;   // 1/sqrt(128)
        q[t*TS + d + 0] = tf32f(v4.x * sc);
        q[t*TS + d + 1] = tf32f(v4.y * sc);
        q[t*TS + d + 2] = tf32f(v4.z * sc);
        q[t*TS + d + 3] = tf32f(v4.w * sc);
    }

    float oacc[2][4];
    #pragma unroll
    for (int nt = 0; nt < 2; nt++)
        #pragma unroll
        for (int j = 0; j < 4; j++) oacc[nt][j] = 0.f;

    if (ntiles > 0) {
        #pragma unroll
        for (int j = 0; j < 8; j++) {
            int c = tid + j*256;
            int r = c >> 5, col = c & 31;
            int s = sb + r;
            const float* src; int sz;
            if (s < sp && s < se) { src = kc + (size_t)s*D_ + col*4; sz = 16; }
            else if (s < se)      { src = kf + (size_t)(s - sp)*QKV_N + col*4; sz = 16; }
            else                  { src = kc; sz = 0; }
            cpa16(Ku + (uint32_t)(r*TS + col*4)*4u, src, sz);
        }
        cpa_commit();
        cpa_wait0();
    }
    __syncthreads();

    for (int ti = 0; ti < ntiles; ti++) {
        int s0 = sb + ti * TILE;
        #pragma unroll
        for (int j = 0; j < 8; j++) {
            int c = tid + j*256;
            int r = c >> 5, col = c & 31;
            int s = s0 + r;
            const float* src; int sz;
            if (s < sp && s < se) { src = vc + (size_t)s*D_ + col*4; sz = 16; }
            else if (s < se)      { src = vf + (size_t)(s - sp)*QKV_N + col*4; sz = 16; }
            else                  { src = vc; sz = 0; }
            cpa16(Vu + (uint32_t)(r*TS + col*4)*4u, src, sz);
        }
        cpa_commit();

        {
            float sc2[4] = {0.f, 0.f, 0.f, 0.f};
            #pragma unroll
            for (int ks = 0; ks < 16; ks++) {
                uint32_t a0 = __float_as_uint(q[g*TS + 8*ks + c4]);
                uint32_t a2 = __float_as_uint(q[g*TS + 8*ks + c4 + 4]);
                const float* kb = Kbuf + (size_t)(8*w + g)*TS + 8*ks + c4;
                mma8(sc2, a0, a2, __float_as_uint(kb[0]), __float_as_uint(kb[4]));
            }
            *(float2*)(p + g*PS + 8*w + 2*c4) = make_float2(sc2[0], sc2[1]);
        }
        __syncthreads();

        bool more = (ti + 1 < ntiles);
        if (more) {
            int s0n = s0 + TILE;
            #pragma unroll
            for (int j = 0; j < 8; j++) {
                int c = tid + j*256;
                int r = c >> 5, col = c & 31;
                int s = s0n + r;
                const float* src; int sz;
                if (s < sp && s < se) { src = kc + (size_t)s*D_ + col*4; sz = 16; }
                else if (s < se)      { src = kf + (size_t)(s - sp)*QKV_N + col*4; sz = 16; }
                else                  { src = kc; sz = 0; }
                cpa16(Ku + (uint32_t)(r*TS + col*4)*4u, src, sz);
            }
            cpa_commit();
        }

        {
            int t = w;
            float v0 = p[t*PS + lane];
            float v1 = p[t*PS + lane + 32];
            int sg0 = s0 + lane, sg1 = s0 + lane + 32;
            bool ok0 = (sg0 < se) && (!causal || sg0 <= t);
            bool ok1 = (sg1 < se) && (!causal || sg1 <= t);
            v0 = ok0 ? v0 : -1e30f;
            v1 = ok1 ? v1 : -1e30f;
            float mx = fmaxf(v0, v1);
            #pragma unroll
            for (int o = 16; o > 0; o >>= 1)
                mx = fmaxf(mx, __shfl_xor_sync(0xffffffffu, mx, o));
            float mold = mbuf[t];
            float mnew = fmaxf(mold, mx);
            float e0 = ok0 ? tf32f(__expf(v0 - mnew)) : 0.f;
            float e1 = ok1 ? tf32f(__expf(v1 - mnew)) : 0.f;
            p[t*PS + lane]      = e0;
            p[t*PS + lane + 32] = e1;
            float sum = e0 + e1;
            #pragma unroll
            for (int o = 16; o > 0; o >>= 1)
                sum += __shfl_xor_sync(0xffffffffu, sum, o);
            if (lane == 0) {
                float cc = __expf(mold - mnew);
                cbuf[t] = cc;
                lbuf[t] = lbuf[t] * cc + sum;
                mbuf[t] = mnew;
            }
        }
        if (more) cpa_wait1(); else cpa_wait0();
        __syncthreads();

        {
            float cf = cbuf[g];
            #pragma unroll
            for (int nt = 0; nt < 2; nt++) { oacc[nt][0] *= cf; oacc[nt][1] *= cf; }
        }

        #pragma unroll
        for (int ks = 0; ks < 8; ks++) {
            uint32_t a0 = __float_as_uint(p[g*PS + 8*ks + c4]);
            uint32_t a2 = __float_as_uint(p[g*PS + 8*ks + c4 + 4]);
            #pragma unroll
            for (int nt = 0; nt < 2; nt++) {
                int n0 = 16*w + 8*nt;
                uint32_t b0 = __float_as_uint(Vbuf[(size_t)(8*ks + c4)*TS + n0 + g]);
                uint32_t b1 = __float_as_uint(Vbuf[(size_t)(8*ks + c4 + 4)*TS + n0 + g]);
                mma8(oacc[nt], a0, a2, b0, b1);
            }
        }
        if (more) cpa_wait0();
        __syncthreads();
    }

    {
        float* po = g_part + (size_t)blockIdx.x * 1024;
        #pragma unroll
        for (int nt = 0; nt < 2; nt++) {
            int d0 = 16*w + 8*nt + 2*c4;
            *(float2*)(po + g*128 + d0) = make_float2(oacc[nt][0], oacc[nt][1]);
        }
        if (tid < 8)
            g_ml[(size_t)blockIdx.x * 8 + tid] = make_float2(mbuf[tid], lbuf[tid]);
    }
}

// ---------------------------------------------------------------------------
__global__ void attn_merge() {
    int wi = blockIdx.x * 8 + (threadIdx.x >> 5);   // bh*8 + t
    int lane = threadIdx.x & 31;
    int bh = wi >> 3, t = wi & 7;
    int b = bh >> 4, h = bh & 15;
    int d0 = lane * 4;

    float mstar = -1e30f;
    float2 ml[SPLITS];
    #pragma unroll
    for (int s = 0; s < SPLITS; s++) {
        ml[s] = g_ml[(size_t)(bh*SPLITS + s) * 8 + t];
        mstar = fmaxf(mstar, ml[s].x);
    }
    float lstar = 0.f;
    float4 acc = make_float4(0.f, 0.f, 0.f, 0.f);
    #pragma unroll
    for (int s = 0; s < SPLITS; s++) {
        float ws = __expf(ml[s].x - mstar);
        lstar += ws * ml[s].y;
        float4 o = *(const float4*)(g_part + (size_t)(bh*SPLITS + s)*1024 + t*128 + d0);
        acc.x += ws*o.x; acc.y += ws*o.y; acc.z += ws*o.z; acc.w += ws*o.w;
    }
    float inv = (lstar > 0.f) ? (1.f / lstar) : 0.f;
    acc.x *= inv; acc.y *= inv; acc.z *= inv; acc.w *= inv;
    *(float4*)(g_y + (size_t)(b*T_ + t)*C_ + h*D_ + d0) = acc;
}

// ---------------------------------------------------------------------------
extern "C" void kernel_launch(void* const* d_in, const int* in_sizes, int n_in,
                              void* d_out, int out_size) {
    const float* x       = (const float*)d_in[0];
    const float* k_cache = (const float*)d_in[1];
    const float* v_cache = (const float*)d_in[2];
    const float* w_attn  = (const float*)d_in[3];
    const float* b_attn  = (const float*)d_in[4];
    const float* w_proj  = (const float*)d_in[5];
    const float* b_proj  = (const float*)d_in[6];
    const int*   sp      = (const int*)d_in[7];
    const int*   ic      = (const int*)d_in[8];
    float* out = (float*)d_out;

    float *qkv, *y, *gp;
    cudaGetSymbolAddress((void**)&qkv, g_qkv);
    cudaGetSymbolAddress((void**)&y, g_y);
    cudaGetSymbolAddress((void**)&gp, g_gp);

    cudaFuncSetAttribute(bf16_gemm, cudaFuncAttributeMaxDynamicSharedMemorySize,
                         G3SMEMB);
    cudaFuncSetAttribute(attn_kernel, cudaFuncAttributeMaxDynamicSharedMemorySize,
                         ASM_FLOATS * 4);

    // shift ncu capture window onto the QKV GEMM (4th launch)
    dummy_k<<<1, 1>>>();
    dummy_k<<<1, 1>>>();
    dummy_k<<<1, 1>>>();

    // 1) QKV partials (48 n-blocks x split-K 6 = 288 CTAs, 2/SM), then reduce+bias
    bf16_gemm<<<dim3(48, 1, 6), 256, G3SMEMB>>>(x, w_attn, gp, QKV_N, C_, 352);
    reduce_add<<<(M_*QKV_N/4 + 255)/256, 256>>>(qkv, gp, b_attn,
                                                QKV_N, M_*QKV_N/4, 6);

    // 2) attention split-S -> partials, then merge -> g_y
    attn_kernel<<<B_*H_*SPLITS, 256, ASM_FLOATS*4>>>(k_cache, v_cache, sp, ic);
    attn_merge<<<256, 256>>>();

    // 3) proj partials (16 n-blocks x split-K 16 = 256 CTAs), then reduce+bias
    bf16_gemm<<<dim3(16, 1, 16), 256, G3SMEMB>>>(y, w_proj, gp, C_, C_, 128);
    reduce_add<<<(M_*C_/4 + 255)/256, 256>>>(out, gp, b_proj,
                                             C_, M_*C_/4, 16);
}

// round 15
// speedup vs baseline: 1.0349x; 1.0349x over previous
#include <cuda_runtime.h>
#include <cstdint>

#define B_ 16
#define T_ 8
#define C_ 2048
#define H_ 16
#define D_ 128
#define MAXSEQ 4096
#define QKV_N (3*C_)   // 6144
#define M_ (B_*T_)     // 128
#define SPLITS 8

// Scratch (no allocations allowed) -------------------------------------------
__device__ float  g_qkv[M_ * QKV_N];               // [b*T+t][3C]  q|k|v
__device__ float  g_y[M_ * C_];                    // attention output
__device__ float  g_part[B_*H_*SPLITS * 8 * 128];  // unnormalized O per split
__device__ float2 g_ml[B_*H_*SPLITS * 8];          // (m,l) per split per t
__device__ float  g_gp[6 * M_ * QKV_N];            // GEMM split-K partials

// ---------------------------------------------------------------------------
__device__ __forceinline__ float tf32f(float x) {
    uint32_t r; asm("cvt.rna.tf32.f32 %0, %1;" : "=r"(r) : "f"(x));
    return __uint_as_float(r);
}
// pack two floats to bf16x2: vlo -> low half (element k), vhi -> high (k+1)
__device__ __forceinline__ uint32_t bf2(float vlo, float vhi) {
    uint32_t r; asm("cvt.rn.bf16x2.f32 %0, %1, %2;" : "=r"(r) : "f"(vhi), "f"(vlo));
    return r;
}
__device__ __forceinline__ void mma8(float* d, uint32_t a0, uint32_t a2,
                                     uint32_t b0, uint32_t b1) {
    const uint32_t z = 0;
    asm volatile(
        "mma.sync.aligned.m16n8k8.row.col.f32.tf32.tf32.f32 "
        "{%0,%1,%2,%3}, {%4,%5,%6,%7}, {%8,%9}, {%0,%1,%2,%3};"
        : "+f"(d[0]), "+f"(d[1]), "+f"(d[2]), "+f"(d[3])
        : "r"(a0), "r"(z), "r"(a2), "r"(z), "r"(b0), "r"(b1));
}
__device__ __forceinline__ void mma16(float* d, const uint32_t* a,
                                      uint32_t b0, uint32_t b1) {
    asm volatile(
        "mma.sync.aligned.m16n8k16.row.col.f32.bf16.bf16.f32 "
        "{%0,%1,%2,%3}, {%4,%5,%6,%7}, {%8,%9}, {%0,%1,%2,%3};"
        : "+f"(d[0]), "+f"(d[1]), "+f"(d[2]), "+f"(d[3])
        : "r"(a[0]), "r"(a[1]), "r"(a[2]), "r"(a[3]), "r"(b0), "r"(b1));
}
__device__ __forceinline__ void cpa16(uint32_t dst, const void* src, int srcsize) {
    asm volatile("cp.async.cg.shared.global [%0], [%1], 16, %2;"
                 :: "r"(dst), "l"(src), "r"(srcsize) : "memory");
}
__device__ __forceinline__ void cpa_commit() {
    asm volatile("cp.async.commit_group;" ::: "memory");
}
__device__ __forceinline__ void cpa_wait0() {
    asm volatile("cp.async.wait_group 0;" ::: "memory");
}
__device__ __forceinline__ void cpa_wait1() {
    asm volatile("cp.async.wait_group 1;" ::: "memory");
}

// dummy: shifts ncu's capture window onto the QKV GEMM
__global__ void dummy_k() {}

// ---------------------------------------------------------------------------
// 3xBF16 GEMM (hh + hl + lh, mma.m16n8k16), split-K partial output (no atomics).
// CTA tile 128x128, BK=16, 256 threads, 8 warps (4m x 2n) of m32n64.
// __launch_bounds__(256,2): cap 128 regs -> 2 CTAs/SM (R13 had 138 regs -> 1/SM).
#define MSu 260
#define BSu 260
#define STGu (8*MSu + 8*BSu)         // 4160 u32 per stage
#define G3SMEMB (2*STGu*4)           // 33280 B

__global__ void __launch_bounds__(256, 2)
bf16_gemm(const float* __restrict__ A, const float* __restrict__ W,
          float* __restrict__ P, int N, int K, int kLen) {
    extern __shared__ float sh[];
    uint32_t* shu = (uint32_t*)sh;

    int tid  = threadIdx.x;
    int lane = tid & 31, w = tid >> 5;
    int g = lane >> 2, c4 = lane & 3;
    int n0 = blockIdx.x * 128;
    int k0 = blockIdx.z * kLen;
    int rem = K - k0;
    int iters = ((kLen < rem) ? kLen : rem) >> 4;
    int wm = (w & 3) * 32;            // warp grid 4 (m) x 2 (n)
    int wn = (w >> 2) * 64;

    // A loader: row = tid>>1 (0..127), k-half = (tid&1)*8 -> 4 kpairs
    int arow = tid >> 1, ah = (tid & 1) * 8;
    // B loader: warp w owns kpair w (rows 2w, 2w+1); lane covers 4 n-cols
    int bn4 = lane * 4, bkp = w;

    float acc[2][8][4];
    #pragma unroll
    for (int mt = 0; mt < 2; mt++)
        #pragma unroll
        for (int nt = 0; nt < 8; nt++)
            #pragma unroll
            for (int j = 0; j < 4; j++) acc[mt][nt][j] = 0.f;

    float4 ra0, ra1, rb0, rb1;

    // ---- prefetch iter 0 ----
    {
        const float* pa = A + (size_t)arow * K + k0 + ah;
        ra0 = *(const float4*)pa; ra1 = *(const float4*)(pa + 4);
        rb0 = *(const float4*)(W + (size_t)(k0 + 2*bkp)     * N + n0 + bn4);
        rb1 = *(const float4*)(W + (size_t)(k0 + 2*bkp + 1) * N + n0 + bn4);
    }
    // ---- convert + store stage 0 ----
    {
        uint32_t* as = shu;
        uint32_t* bs = shu + 8*MSu;
        float v[8] = {ra0.x, ra0.y, ra0.z, ra0.w, ra1.x, ra1.y, ra1.z, ra1.w};
        #pragma unroll
        for (int j = 0; j < 4; j++) {
            uint32_t hi = bf2(v[2*j], v[2*j+1]);
            float h0 = __uint_as_float(hi << 16);
            float h1 = __uint_as_float(hi & 0xffff0000u);
            uint32_t lo = bf2(v[2*j] - h0, v[2*j+1] - h1);
            int kp = (ah >> 1) + j;
            *(uint2*)(as + kp*MSu + 2*arow) = make_uint2(hi, lo);
        }
        float v0[4] = {rb0.x, rb0.y, rb0.z, rb0.w};
        float v1[4] = {rb1.x, rb1.y, rb1.z, rb1.w};
        #pragma unroll
        for (int q = 0; q < 4; q++) {
            uint32_t hi = bf2(v0[q], v1[q]);
            float h0 = __uint_as_float(hi << 16);
            float h1 = __uint_as_float(hi & 0xffff0000u);
            uint32_t lo = bf2(v0[q] - h0, v1[q] - h1);
            *(uint2*)(bs + bkp*BSu + 2*(bn4 + q)) = make_uint2(hi, lo);
        }
    }
    __syncthreads();

    for (int it = 0; it < iters; it++) {
        if (it + 1 < iters) {
            int kb = k0 + (it+1)*16;
            const float* pa = A + (size_t)arow * K + kb + ah;
            ra0 = *(const float4*)pa; ra1 = *(const float4*)(pa + 4);
            rb0 = *(const float4*)(W + (size_t)(kb + 2*bkp)     * N + n0 + bn4);
            rb1 = *(const float4*)(W + (size_t)(kb + 2*bkp + 1) * N + n0 + bn4);
        }
        // ---- compute on stage it&1 ----
        {
            const uint32_t* as = shu + (it & 1) * STGu;
            const uint32_t* bs = as + 8*MSu;
            uint32_t ahi[2][4], alo[2][4];
            #pragma unroll
            for (int mt = 0; mt < 2; mt++) {
                int m0 = wm + 16*mt + g;
                uint2 t00 = *(const uint2*)(as + c4*MSu     + 2*m0);
                uint2 t10 = *(const uint2*)(as + c4*MSu     + 2*(m0+8));
                uint2 t01 = *(const uint2*)(as + (c4+4)*MSu + 2*m0);
                uint2 t11 = *(const uint2*)(as + (c4+4)*MSu + 2*(m0+8));
                ahi[mt][0] = t00.x; ahi[mt][1] = t10.x; ahi[mt][2] = t01.x; ahi[mt][3] = t11.x;
                alo[mt][0] = t00.y; alo[mt][1] = t10.y; alo[mt][2] = t01.y; alo[mt][3] = t11.y;
            }
            #pragma unroll
            for (int nt = 0; nt < 8; nt++) {
                int nc = wn + 8*nt + g;
                uint2 b0 = *(const uint2*)(bs + c4*BSu     + 2*nc);
                uint2 b1 = *(const uint2*)(bs + (c4+4)*BSu + 2*nc);
                #pragma unroll
                for (int mt = 0; mt < 2; mt++) {
                    mma16(acc[mt][nt], ahi[mt], b0.x, b1.x);   // hh
                    mma16(acc[mt][nt], ahi[mt], b0.y, b1.y);   // hl
                    mma16(acc[mt][nt], alo[mt], b0.x, b1.x);   // lh
                }
            }
        }
        if (it + 1 < iters) {
            uint32_t* as = shu + ((it+1) & 1) * STGu;
            uint32_t* bs = as + 8*MSu;
            float v[8] = {ra0.x, ra0.y, ra0.z, ra0.w, ra1.x, ra1.y, ra1.z, ra1.w};
            #pragma unroll
            for (int j = 0; j < 4; j++) {
                uint32_t hi = bf2(v[2*j], v[2*j+1]);
                float h0 = __uint_as_float(hi << 16);
                float h1 = __uint_as_float(hi & 0xffff0000u);
                uint32_t lo = bf2(v[2*j] - h0, v[2*j+1] - h1);
                int kp = (ah >> 1) + j;
                *(uint2*)(as + kp*MSu + 2*arow) = make_uint2(hi, lo);
            }
            float v0[4] = {rb0.x, rb0.y, rb0.z, rb0.w};
            float v1[4] = {rb1.x, rb1.y, rb1.z, rb1.w};
            #pragma unroll
            for (int q = 0; q < 4; q++) {
                uint32_t hi = bf2(v0[q], v1[q]);
                float h0 = __uint_as_float(hi << 16);
                float h1 = __uint_as_float(hi & 0xffff0000u);
                uint32_t lo = bf2(v0[q] - h0, v1[q] - h1);
                *(uint2*)(bs + bkp*BSu + 2*(bn4 + q)) = make_uint2(hi, lo);
            }
        }
        __syncthreads();
    }

    // ---- epilogue: plain stores to split-private partial buffer ----
    float* dst = P + (size_t)blockIdx.z * ((size_t)M_ * N);
    #pragma unroll
    for (int mt = 0; mt < 2; mt++)
        #pragma unroll
        for (int nt = 0; nt < 8; nt++) {
            int m   = wm + 16*mt + g;
            int col = n0 + wn + 8*nt + 2*c4;
            *(float2*)&dst[(size_t)m * N + col] =
                make_float2(acc[mt][nt][0], acc[mt][nt][1]);
            *(float2*)&dst[(size_t)(m+8) * N + col] =
                make_float2(acc[mt][nt][2], acc[mt][nt][3]);
        }
}

// ---------------------------------------------------------------------------
// dst[m][n] = bias[n] + sum_s P[s][m][n]   (float4-vectorized)
__global__ void reduce_add(float* __restrict__ dst, const float* __restrict__ P,
                           const float* __restrict__ bias,
                           int N, int total4, int nsplits) {
    int i = blockIdx.x * blockDim.x + threadIdx.x;
    if (i >= total4) return;
    int n = (i << 2) % N;
    float4 s = *(const float4*)(bias + n);
    for (int sp = 0; sp < nsplits; sp++) {
        float4 p = ((const float4*)P)[(size_t)sp * total4 + i];
        s.x += p.x; s.y += p.y; s.z += p.z; s.w += p.w;
    }
    ((float4*)dst)[i] = s;
}

// ---------------------------------------------------------------------------
// Flash attention, split-S(8), tf32 mma, TILE=64, cp.async double-buffered.
// (unchanged from best round)
#define TILE 64
#define TS 132
#define PS 68
#define ASM_FLOATS (8*TS + 2*TILE*TS + 8*PS + 24)   // 74080 B

__global__ void __launch_bounds__(256, 3)
attn_kernel(const float* __restrict__ k_cache,
            const float* __restrict__ v_cache,
            const int* __restrict__ sp_ptr,
            const int* __restrict__ causal_ptr) {
    extern __shared__ float sm[];
    float* q    = sm;                   // 8 x TS
    float* Kbuf = sm + 8*TS;            // TILE x TS
    float* Vbuf = Kbuf + TILE*TS;       // TILE x TS
    float* p    = Vbuf + TILE*TS;       // 8 x PS
    float* mbuf = p + 8*PS;
    float* lbuf = mbuf + 8;
    float* cbuf = lbuf + 8;

    uint32_t Ku = (uint32_t)__cvta_generic_to_shared(Kbuf);
    uint32_t Vu = (uint32_t)__cvta_generic_to_shared(Vbuf);

    int tid  = threadIdx.x;
    int lane = tid & 31;
    int w    = tid >> 5;
    int bh    = blockIdx.x >> 3;
    int split = blockIdx.x & 7;
    int b = bh >> 4, h = bh & 15;
    int sp = *sp_ptr;
    int causal = *causal_ptr;
    int S = sp + T_;
    int SLEN = (S + SPLITS - 1) / SPLITS;
    int sb = split * SLEN;
    int se = min(S, sb + SLEN);
    int ntiles = (se > sb) ? (se - sb + TILE - 1) / TILE : 0;
    int g = lane >> 2, c4 = lane & 3;

    const float* kc = k_cache + (size_t)bh * MAXSEQ * D_;
    const float* vc = v_cache + (size_t)bh * MAXSEQ * D_;
    const float* kf = g_qkv + (size_t)b * T_ * QKV_N + C_   + h*D_;
    const float* vf = g_qkv + (size_t)b * T_ * QKV_N + 2*C_ + h*D_;

    if (tid < 8) { mbuf[tid] = -1e30f; lbuf[tid] = 0.f; }
    {
        int t = tid >> 5;
        int d = lane * 4;
        float4 v4 = *(const float4*)(g_qkv + (size_t)(b*T_ + t)*QKV_N + h*D_ + d);
        const float sc = 0.08838834764831845f;   // 1/sqrt(128)
        q[t*TS + d + 0] = tf32f(v4.x * sc);
        q[t*TS + d + 1] = tf32f(v4.y * sc);
        q[t*TS + d + 2] = tf32f(v4.z * sc);
        q[t*TS + d + 3] = tf32f(v4.w * sc);
    }

    float oacc[2][4];
    #pragma unroll
    for (int nt = 0; nt < 2; nt++)
        #pragma unroll
        for (int j = 0; j < 4; j++) oacc[nt][j] = 0.f;

    if (ntiles > 0) {
        #pragma unroll
        for (int j = 0; j < 8; j++) {
            int c = tid + j*256;
            int r = c >> 5, col = c & 31;
            int s = sb + r;
            const float* src; int sz;
            if (s < sp && s < se) { src = kc + (size_t)s*D_ + col*4; sz = 16; }
            else if (s < se)      { src = kf + (size_t)(s - sp)*QKV_N + col*4; sz = 16; }
            else                  { src = kc; sz = 0; }
            cpa16(Ku + (uint32_t)(r*TS + col*4)*4u, src, sz);
        }
        cpa_commit();
        cpa_wait0();
    }
    __syncthreads();

    for (int ti = 0; ti < ntiles; ti++) {
        int s0 = sb + ti * TILE;
        #pragma unroll
        for (int j = 0; j < 8; j++) {
            int c = tid + j*256;
            int r = c >> 5, col = c & 31;
            int s = s0 + r;
            const float* src; int sz;
            if (s < sp && s < se) { src = vc + (size_t)s*D_ + col*4; sz = 16; }
            else if (s < se)      { src = vf + (size_t)(s - sp)*QKV_N + col*4; sz = 16; }
            else                  { src = vc; sz = 0; }
            cpa16(Vu + (uint32_t)(r*TS + col*4)*4u, src, sz);
        }
        cpa_commit();

        {
            float sc2[4] = {0.f, 0.f, 0.f, 0.f};
            #pragma unroll
            for (int ks = 0; ks < 16; ks++) {
                uint32_t a0 = __float_as_uint(q[g*TS + 8*ks + c4]);
                uint32_t a2 = __float_as_uint(q[g*TS + 8*ks + c4 + 4]);
                const float* kb = Kbuf + (size_t)(8*w + g)*TS + 8*ks + c4;
                mma8(sc2, a0, a2, __float_as_uint(kb[0]), __float_as_uint(kb[4]));
            }
            *(float2*)(p + g*PS + 8*w + 2*c4) = make_float2(sc2[0], sc2[1]);
        }
        __syncthreads();

        bool more = (ti + 1 < ntiles);
        if (more) {
            int s0n = s0 + TILE;
            #pragma unroll
            for (int j = 0; j < 8; j++) {
                int c = tid + j*256;
                int r = c >> 5, col = c & 31;
                int s = s0n + r;
                const float* src; int sz;
                if (s < sp && s < se) { src = kc + (size_t)s*D_ + col*4; sz = 16; }
                else if (s < se)      { src = kf + (size_t)(s - sp)*QKV_N + col*4; sz = 16; }
                else                  { src = kc; sz = 0; }
                cpa16(Ku + (uint32_t)(r*TS + col*4)*4u, src, sz);
            }
            cpa_commit();
        }

        {
            int t = w;
            float v0 = p[t*PS + lane];
            float v1 = p[t*PS + lane + 32];
            int sg0 = s0 + lane, sg1 = s0 + lane + 32;
            bool ok0 = (sg0 < se) && (!causal || sg0 <= t);
            bool ok1 = (sg1 < se) && (!causal || sg1 <= t);
            v0 = ok0 ? v0 : -1e30f;
            v1 = ok1 ? v1 : -1e30f;
            float mx = fmaxf(v0, v1);
            #pragma unroll
            for (int o = 16; o > 0; o >>= 1)
                mx = fmaxf(mx, __shfl_xor_sync(0xffffffffu, mx, o));
            float mold = mbuf[t];
            float mnew = fmaxf(mold, mx);
            float e0 = ok0 ? tf32f(__expf(v0 - mnew)) : 0.f;
            float e1 = ok1 ? tf32f(__expf(v1 - mnew)) : 0.f;
            p[t*PS + lane]      = e0;
            p[t*PS + lane + 32] = e1;
            float sum = e0 + e1;
            #pragma unroll
            for (int o = 16; o > 0; o >>= 1)
                sum += __shfl_xor_sync(0xffffffffu, sum, o);
            if (lane == 0) {
                float cc = __expf(mold - mnew);
                cbuf[t] = cc;
                lbuf[t] = lbuf[t] * cc + sum;
                mbuf[t] = mnew;
            }
        }
        if (more) cpa_wait1(); else cpa_wait0();
        __syncthreads();

        {
            float cf = cbuf[g];
            #pragma unroll
            for (int nt = 0; nt < 2; nt++) { oacc[nt][0] *= cf; oacc[nt][1] *= cf; }
        }

        #pragma unroll
        for (int ks = 0; ks < 8; ks++) {
            uint32_t a0 = __float_as_uint(p[g*PS + 8*ks + c4]);
            uint32_t a2 = __float_as_uint(p[g*PS + 8*ks + c4 + 4]);
            #pragma unroll
            for (int nt = 0; nt < 2; nt++) {
                int n0 = 16*w + 8*nt;
                uint32_t b0 = __float_as_uint(Vbuf[(size_t)(8*ks + c4)*TS + n0 + g]);
                uint32_t b1 = __float_as_uint(Vbuf[(size_t)(8*ks + c4 + 4)*TS + n0 + g]);
                mma8(oacc[nt], a0, a2, b0, b1);
            }
        }
        if (more) cpa_wait0();
        __syncthreads();
    }

    {
        float* po = g_part + (size_t)blockIdx.x * 1024;
        #pragma unroll
        for (int nt = 0; nt < 2; nt++) {
            int d0 = 16*w + 8*nt + 2*c4;
            *(float2*)(po + g*128 + d0) = make_float2(oacc[nt][0], oacc[nt][1]);
        }
        if (tid < 8)
            g_ml[(size_t)blockIdx.x * 8 + tid] = make_float2(mbuf[tid], lbuf[tid]);
    }
}

// ---------------------------------------------------------------------------
__global__ void attn_merge() {
    int wi = blockIdx.x * 8 + (threadIdx.x >> 5);   // bh*8 + t
    int lane = threadIdx.x & 31;
    int bh = wi >> 3, t = wi & 7;
    int b = bh >> 4, h = bh & 15;
    int d0 = lane * 4;

    float mstar = -1e30f;
    float2 ml[SPLITS];
    #pragma unroll
    for (int s = 0; s < SPLITS; s++) {
        ml[s] = g_ml[(size_t)(bh*SPLITS + s) * 8 + t];
        mstar = fmaxf(mstar, ml[s].x);
    }
    float lstar = 0.f;
    float4 acc = make_float4(0.f, 0.f, 0.f, 0.f);
    #pragma unroll
    for (int s = 0; s < SPLITS; s++) {
        float ws = __expf(ml[s].x - mstar);
        lstar += ws * ml[s].y;
        float4 o = *(const float4*)(g_part + (size_t)(bh*SPLITS + s)*1024 + t*128 + d0);
        acc.x += ws*o.x; acc.y += ws*o.y; acc.z += ws*o.z; acc.w += ws*o.w;
    }
    float inv = (lstar > 0.f) ? (1.f / lstar) : 0.f;
    acc.x *= inv; acc.y *= inv; acc.z *= inv; acc.w *= inv;
    *(float4*)(g_y + (size_t)(b*T_ + t)*C_ + h*D_ + d0) = acc;
}

// ---------------------------------------------------------------------------
extern "C" void kernel_launch(void* const* d_in, const int* in_sizes, int n_in,
                              void* d_out, int out_size) {
    const float* x       = (const float*)d_in[0];
    const float* k_cache = (const float*)d_in[1];
    const float* v_cache = (const float*)d_in[2];
    const float* w_attn  = (const float*)d_in[3];
    const float* b_attn  = (const float*)d_in[4];
    const float* w_proj  = (const float*)d_in[5];
    const float* b_proj  = (const float*)d_in[6];
    const int*   sp      = (const int*)d_in[7];
    const int*   ic      = (const int*)d_in[8];
    float* out = (float*)d_out;

    float *qkv, *y, *gp;
    cudaGetSymbolAddress((void**)&qkv, g_qkv);
    cudaGetSymbolAddress((void**)&y, g_y);
    cudaGetSymbolAddress((void**)&gp, g_gp);

    cudaFuncSetAttribute(bf16_gemm, cudaFuncAttributeMaxDynamicSharedMemorySize,
                         G3SMEMB);
    cudaFuncSetAttribute(attn_kernel, cudaFuncAttributeMaxDynamicSharedMemorySize,
                         ASM_FLOATS * 4);

    // shift ncu capture window onto the QKV GEMM (4th launch)
    dummy_k<<<1, 1>>>();
    dummy_k<<<1, 1>>>();
    dummy_k<<<1, 1>>>();

    // 1) QKV partials (48 n-blocks x split-K 6 = 288 CTAs, 2/SM), then reduce+bias
    bf16_gemm<<<dim3(48, 1, 6), 256, G3SMEMB>>>(x, w_attn, gp, QKV_N, C_, 352);
    reduce_add<<<(M_*QKV_N/4 + 255)/256, 256>>>(qkv, gp, b_attn,
                                                QKV_N, M_*QKV_N/4, 6);

    // 2) attention split-S -> partials, then merge -> g_y
    attn_kernel<<<B_*H_*SPLITS, 256, ASM_FLOATS*4>>>(k_cache, v_cache, sp, ic);
    attn_merge<<<256, 256>>>();

    // 3) proj partials (16 n-blocks x split-K 16 = 256 CTAs), then reduce+bias
    bf16_gemm<<<dim3(16, 1, 16), 256, G3SMEMB>>>(y, w_proj, gp, C_, C_, 128);
    reduce_add<<<(M_*C_/4 + 255)/256, 256>>>(out, gp, b_proj,
                                             C_, M_*C_/4, 16);
}